// round 17
// baseline (speedup 1.0000x reference)
#include <cuda_runtime.h>
#include <cuda_fp16.h>
#include <math.h>
#include <stdint.h>

// Problem constants
#define BT_  16384   // B*T
#define F_   64
#define E_   64
#define H_   8
#define P_   512
#define K_   1024    // 2*F*H

// GEMM tiling: CTA 128x256, BK=64, 16 k-steps; A produced by dedicated warp
#define BM 128
#define BN 256
#define BK 64
#define NT (K_ / BK)     // 16
#define ROWB 144         // 128B payload + 16B pad (conflict-free ldmatrix)
#define A_BYTES (BM * ROWB)   // 18432
#define B_BYTES (BN * ROWB)   // 36864

// smem layout: w1 table (4KB) | b1 table (4KB) | A x3 | B x3
#define TBLW_OFF 0
#define TBLB_OFF 4096
#define A_OFF    8192
#define B_OFF    (A_OFF + 3 * A_BYTES)          // 63488
#define SMEM_BYTES (B_OFF + 3 * B_BYTES)        // 174080

#define THREADS 288      // 8 MMA warps + 1 producer warp

// Scratch (static device globals)
__device__ __half g_Wt[P_ * K_];      // folded weights [P][K] fp16 (1MB)
__device__ float  g_bias[P_];

// ---------------------------------------------------------------------------
// helpers
// ---------------------------------------------------------------------------
__device__ __forceinline__ uint32_t smem_u32(const void* p) {
    uint32_t a;
    asm("{ .reg .u64 t; cvta.to.shared.u64 t, %1; cvt.u32.u64 %0, t; }" : "=r"(a) : "l"(p));
    return a;
}

__device__ __forceinline__ void cp16(uint32_t dst, const void* src) {
    asm volatile("cp.async.cg.shared.global [%0], [%1], 16;" :: "r"(dst), "l"(src) : "memory");
}

#define CP_COMMIT()  asm volatile("cp.async.commit_group;" ::: "memory")
#define CP_WAIT(n)   asm volatile("cp.async.wait_group %0;" :: "n"(n) : "memory")

__device__ __forceinline__ void ldmx4(uint32_t r[4], uint32_t addr) {
    asm volatile("ldmatrix.sync.aligned.m8n8.x4.shared.b16 {%0,%1,%2,%3}, [%4];"
                 : "=r"(r[0]), "=r"(r[1]), "=r"(r[2]), "=r"(r[3]) : "r"(addr));
}

__device__ __forceinline__ void mma_f16(float c[4], const uint32_t a[4],
                                        const uint32_t b0, const uint32_t b1) {
    asm volatile(
        "mma.sync.aligned.m16n8k16.row.col.f32.f16.f16.f32 "
        "{%0,%1,%2,%3}, {%4,%5,%6,%7}, {%8,%9}, {%0,%1,%2,%3};"
        : "+f"(c[0]), "+f"(c[1]), "+f"(c[2]), "+f"(c[3])
        : "r"(a[0]), "r"(a[1]), "r"(a[2]), "r"(a[3]), "r"(b0), "r"(b1));
}

__device__ __forceinline__ float tanh_fast(float x) {
    float r;
    asm("tanh.approx.f32 %0, %1;" : "=f"(r) : "f"(x));
    return r;
}

__device__ __forceinline__ uint32_t pack_half2(float lo, float hi) {
    uint32_t r;
    asm("cvt.rn.f16x2.f32 %0, %1, %2;" : "=r"(r) : "f"(hi), "f"(lo));
    return r;
}

// ---------------------------------------------------------------------------
// Kernel 1: fold E into weights; write TRANSPOSED fp16 g_Wt[p][k]; bias.
// grid (F, 2, 2) = 256 blocks; 512 threads, e-split 2-way (measured R15)
// ---------------------------------------------------------------------------
__global__ void __launch_bounds__(512) precompute_W(
        const float* __restrict__ w2v, const float* __restrict__ wx,
        const float* __restrict__ w2t, const float* __restrict__ wt,
        const float* __restrict__ bx,  const float* __restrict__ bt) {
    const int f      = blockIdx.x;
    const int branch = blockIdx.y;
    const int phalf  = blockIdx.z;
    const int tid    = threadIdx.x;
    const int pl     = tid & 255;
    const int eh     = tid >> 8;          // 0 or 1
    const int p      = phalf * 256 + pl;

    const float* __restrict__ w2 = branch ? w2t : w2v;
    const float* __restrict__ wp = branch ? wt  : wx;

    __shared__ float s_w2[H_ * E_];
    __shared__ float red[256][H_];
    s_w2[tid] = w2[f * H_ * E_ + tid];
    __syncthreads();

    float acc[H_];
#pragma unroll
    for (int h = 0; h < H_; h++) acc[h] = 0.f;

    const float* __restrict__ base = wp + (size_t)(f * E_ + eh * 32) * P_ + p;
    const float* __restrict__ s2   = s_w2 + eh * 32;
#pragma unroll 16
    for (int e = 0; e < 32; e++) {
        const float w = base[(size_t)e * P_];
#pragma unroll
        for (int h = 0; h < H_; h++) acc[h] = fmaf(s2[h * E_ + e], w, acc[h]);
    }

    if (eh == 1) {
#pragma unroll
        for (int h = 0; h < H_; h++) red[pl][h] = acc[h];
    }
    __syncthreads();
    if (eh == 0) {
#pragma unroll
        for (int h = 0; h < H_; h++) acc[h] += red[pl][h];
        uint4 st;
        st.x = pack_half2(acc[0], acc[1]); st.y = pack_half2(acc[2], acc[3]);
        st.z = pack_half2(acc[4], acc[5]); st.w = pack_half2(acc[6], acc[7]);
        *(uint4*)&g_Wt[(size_t)p * K_ + branch * 512 + f * H_] = st;
    }

    if (blockIdx.x == 0 && branch == 0 && phalf == 0)
        g_bias[tid] = bx[tid] + bt[tid];
}

// ---------------------------------------------------------------------------
// Fused GEMM with warp-specialized A producer.
// grid (512/BN=2, 16384/BM=128) = 256 CTAs, 288 threads:
//   warps 0-7: ldmatrix + MMA + B cp.async   warp 8: A tanh production
// ---------------------------------------------------------------------------
__device__ __forceinline__ void fill_B(uint32_t dst, int kt, int bn, int tid) {
    const int k0 = kt * BK;
#pragma unroll
    for (int i = 0; i < 8; i++) {
        const int c   = tid + i * 256;
        const int row = c >> 3;
        const int ch  = c & 7;
        cp16(dst + (uint32_t)(row * ROWB + ch * 16),
             g_Wt + (size_t)(bn + row) * K_ + k0 + ch * 8);
    }
}

// one f-value chunk of A production: 8 h values -> one 16B store
__device__ __forceinline__ void produce_A_chunk(char* adst, const float* tblW, const float* tblB,
                                                int tbf, float xi) {
    const float4 wl = *(const float4*)&tblW[tbf];
    const float4 wh = *(const float4*)&tblW[tbf + 4];
    const float4 bl = *(const float4*)&tblB[tbf];
    const float4 bh = *(const float4*)&tblB[tbf + 4];
    uint4 st;
    st.x = pack_half2(tanh_fast(fmaf(xi, wl.x, bl.x)), tanh_fast(fmaf(xi, wl.y, bl.y)));
    st.y = pack_half2(tanh_fast(fmaf(xi, wl.z, bl.z)), tanh_fast(fmaf(xi, wl.w, bl.w)));
    st.z = pack_half2(tanh_fast(fmaf(xi, wh.x, bh.x)), tanh_fast(fmaf(xi, wh.y, bh.y)));
    st.w = pack_half2(tanh_fast(fmaf(xi, wh.z, bh.z)), tanh_fast(fmaf(xi, wh.w, bh.w)));
    *(uint4*)adst = st;
}

__global__ void __launch_bounds__(THREADS, 1) gemm_fused(
        float* __restrict__ C,
        const float* __restrict__ x,   const float* __restrict__ tm,
        const float* __restrict__ w1v, const float* __restrict__ b1v,
        const float* __restrict__ w1t, const float* __restrict__ b1t) {
    extern __shared__ char sm[];
    const uint32_t sbase = smem_u32(sm);
    float* tblW = (float*)(sm + TBLW_OFF);
    float* tblB = (float*)(sm + TBLB_OFF);

    const int tid  = threadIdx.x;
    const int lane = tid & 31;
    const int wid  = tid >> 5;          // 0..8
    const int wm   = (wid & 1) * 64;    // MMA warps: 2 in M
    const int wn   = ((wid >> 1) & 3) * 64;  // 4 in N
    const int bm   = blockIdx.y * BM;
    const int bn   = blockIdx.x * BN;

    // consumer A-producer mapping for the PROLOGUE only (tid<256)
    const int arow  = (tid & 255) >> 1;
    const int ahalf = tid & 1;

    const uint32_t a_lane = (uint32_t)((wm + (lane & 15)) * ROWB + ((lane >> 4) & 1) * 16);
    const uint32_t b_lane = (uint32_t)((wn + (lane & 7) + ((lane >> 4) & 1) * 8) * ROWB
                                       + ((lane >> 3) & 1) * 16);

    // ---- w1/b1 tables into smem (consumers; overlaps fold via PDL) ----
    if (tid < 256) {
        for (int i = tid; i < 512; i += 256) {
            tblW[i]       = w1v[i];
            tblW[512 + i] = w1t[i];
            tblB[i]       = b1v[i];
            tblB[512 + i] = b1t[i];
        }
    }
    __syncthreads();

    float acc[4][8][4];
#pragma unroll
    for (int mt = 0; mt < 4; mt++)
#pragma unroll
        for (int nt = 0; nt < 8; nt++)
#pragma unroll
            for (int i = 0; i < 4; i++) acc[mt][nt][i] = 0.f;

    // ---- prologue: consumers produce A(0), A(1) (overlaps the fold) ----
    if (tid < 256) {
#pragma unroll
        for (int kp = 0; kp < 2; kp++) {
            const int f0 = (kp << 3) + ahalf * 4;     // kt<8 -> branch 0 (x)
            const float4 xv = *(const float4*)&x[(size_t)(bm + arow) * F_ + f0];
            char* adst = sm + A_OFF + kp * A_BYTES + arow * ROWB + ahalf * 64;
#pragma unroll
            for (int i = 0; i < 4; i++)
                produce_A_chunk(adst + i * 16, tblW, tblB, (f0 + i) * 8, (&xv.x)[i]);
        }
    }

    // ---- PDL gate: precompute_W complete before g_Wt reads ----
    cudaGridDependencySynchronize();

    if (tid < 256) {
        fill_B(sbase + B_OFF, 0, bn, tid); CP_COMMIT();
        fill_B(sbase + B_OFF + B_BYTES, 1, bn, tid); CP_COMMIT();
    }

    int bstage = 0;
    for (int kt = 0; kt < NT; kt++) {
        if (tid < 256) CP_WAIT(1);   // B(kt) landed (one commit/iter, exact)
        __syncthreads();             // B(kt)/A(kt) visible; rings recyclable

        const int kprod = kt + 2;

        if (wid < 8) {
            // =========== MMA warps: B refill + pure ldmatrix/MMA ===========
            if (tid < 256) {
                if (kprod < NT) {
                    int ns = bstage + 2; if (ns >= 3) ns -= 3;
                    fill_B(sbase + B_OFF + (uint32_t)(ns * B_BYTES), kprod, bn, tid);
                }
                CP_COMMIT();
            }

            const uint32_t Abase = sbase + A_OFF + (uint32_t)((kt % 3) * A_BYTES);
            const uint32_t Bbase = sbase + B_OFF + (uint32_t)(bstage * B_BYTES);

            uint32_t a[2][4];
            uint32_t b[2][16];
#pragma unroll
            for (int np = 0; np < 4; np++)
                ldmx4(&b[0][np * 4], Bbase + b_lane + (uint32_t)(np * 16 * ROWB));
            ldmx4(a[0], Abase + a_lane);

#pragma unroll
            for (int ks = 0; ks < 4; ks++) {
                const uint32_t* bc = b[ks & 1];
                if (ks < 3) {
                    uint32_t* bnx = b[(ks + 1) & 1];
#pragma unroll
                    for (int np = 0; np < 4; np++)
                        ldmx4(&bnx[np * 4], Bbase + b_lane + (uint32_t)(np * 16 * ROWB + (ks + 1) * 32));
                }
#pragma unroll
                for (int mt = 0; mt < 4; mt++) {
                    if (mt < 3)
                        ldmx4(a[(mt + 1) & 1], Abase + a_lane + (uint32_t)((mt + 1) * 16 * ROWB + ks * 32));
                    else if (ks < 3)
                        ldmx4(a[0], Abase + a_lane + (uint32_t)((ks + 1) * 32));
                    const uint32_t* ac = a[mt & 1];
#pragma unroll
                    for (int nt = 0; nt < 8; nt++)
                        mma_f16(acc[mt][nt], ac, bc[nt * 2], bc[nt * 2 + 1]);
                }
            }
        } else if (kprod < NT) {
            // =========== producer warp: A(kt+2), 4 rows per lane ===========
            const float* src = (kprod >= 8) ? tm : x;
            const int tb = (kprod >= 8) ? 512 : 0;
            const int fb = (kprod & 7) << 3;
            char* abase = sm + A_OFF + (kprod % 3) * A_BYTES;
#pragma unroll
            for (int r4 = 0; r4 < 4; r4++) {
                const int row = lane * 4 + r4;
                const float4 xv0 = *(const float4*)&src[(size_t)(bm + row) * F_ + fb];
                const float4 xv1 = *(const float4*)&src[(size_t)(bm + row) * F_ + fb + 4];
                char* adst = abase + row * ROWB;
#pragma unroll
                for (int i = 0; i < 4; i++) {
                    produce_A_chunk(adst + i * 16,      tblW, tblB, tb + (fb + i) * 8,     (&xv0.x)[i]);
                    produce_A_chunk(adst + 64 + i * 16, tblW, tblB, tb + (fb + 4 + i) * 8, (&xv1.x)[i]);
                }
            }
        }

        bstage++; if (bstage >= 3) bstage = 0;
    }

    // ---- epilogue: bias + store (MMA warps only) ----
    if (wid < 8) {
        const int g  = lane >> 2;
        const int qc = (lane & 3) * 2;
#pragma unroll
        for (int nt = 0; nt < 8; nt++) {
            const int col = bn + wn + nt * 8 + qc;
            const float2 bias = *(const float2*)&g_bias[col];
#pragma unroll
            for (int mt = 0; mt < 4; mt++) {
                const int row = bm + wm + mt * 16 + g;
                float2 v0, v1;
                v0.x = acc[mt][nt][0] + bias.x;
                v0.y = acc[mt][nt][1] + bias.y;
                v1.x = acc[mt][nt][2] + bias.x;
                v1.y = acc[mt][nt][3] + bias.y;
                *(float2*)&C[(size_t)row * P_ + col]       = v0;
                *(float2*)&C[(size_t)(row + 8) * P_ + col] = v1;
            }
        }
    }
}

// ---------------------------------------------------------------------------
// Launch: x, time, w1v, b1v, w2v, w1t, b1t, w2t, wx, bx, wt, bt
// ---------------------------------------------------------------------------
extern "C" void kernel_launch(void* const* d_in, const int* in_sizes, int n_in,
                              void* d_out, int out_size) {
    const float* x    = (const float*)d_in[0];
    const float* tmi  = (const float*)d_in[1];
    const float* w1v  = (const float*)d_in[2];
    const float* b1v  = (const float*)d_in[3];
    const float* w2v  = (const float*)d_in[4];
    const float* w1t  = (const float*)d_in[5];
    const float* b1t  = (const float*)d_in[6];
    const float* w2t  = (const float*)d_in[7];
    const float* wx   = (const float*)d_in[8];
    const float* bx   = (const float*)d_in[9];
    const float* wt   = (const float*)d_in[10];
    const float* bt   = (const float*)d_in[11];
    float* out = (float*)d_out;

    static bool attr_set = false;
    if (!attr_set) {
        cudaFuncSetAttribute(gemm_fused, cudaFuncAttributeMaxDynamicSharedMemorySize, SMEM_BYTES);
        attr_set = true;
    }

    precompute_W<<<dim3(F_, 2, 2), 512>>>(w2v, wx, w2t, wt, bx, bt);

    cudaLaunchConfig_t cfg = {};
    cfg.gridDim  = dim3(P_ / BN, BT_ / BM);
    cfg.blockDim = dim3(THREADS);
    cfg.dynamicSmemBytes = SMEM_BYTES;
    cfg.stream   = 0;
    cudaLaunchAttribute attrs[1];
    attrs[0].id = cudaLaunchAttributeProgrammaticStreamSerialization;
    attrs[0].val.programmaticStreamSerializationAllowed = 1;
    cfg.attrs = attrs;
    cfg.numAttrs = 1;
    cudaLaunchKernelEx(&cfg, gemm_fused, out, x, tmi, w1v, b1v, w1t, b1t);
}